// round 12
// baseline (speedup 1.0000x reference)
#include <cuda_runtime.h>

#define NBv   8
#define ND    512
#define NCHv  3
#define NMIXv 4
#define HD    128
#define NTILE 16

// ---------------- device scratch ----------------
__device__ float g_part[NBv * NCHv * NTILE * HD];  // per-(b,k,tile) layer1 partials

__device__ __forceinline__ float ex2f(float x) {
    float r; asm("ex2.approx.f32 %0, %1;" : "=f"(r) : "f"(x)); return r;
}
__device__ __forceinline__ void pfL1(const void* p) {
    asm volatile("prefetch.global.L1 [%0];" :: "l"(p));
}
__device__ __forceinline__ void pfL2(const void* p) {
    asm volatile("prefetch.global.L2 [%0];" :: "l"(p));
}

// ---------------- shared-memory overlays ----------------
struct Tables {
    float4 A[ND];   // {u0m0, u0m1, u1m0, u1m1}
    float4 B[ND];   // {c0*y, c1*y, s0*y, s1*y}
    float4 C[ND];   // mixes 2,3 u's
    float4 D[ND];   // mixes 2,3 c*y / s*y
    float4 P[ND];   // {P0,P1,P2,P3}
};                                    // 40960 B
struct Reduce {
    float red[8][32][4];              // 4096 B  [csplit][lane][mix]
    float sred[2][HD];                // 1024 B
};

// ---------------- kernel 1: pair + fused layer 1 (R11 verbatim) ------------
__global__ void __launch_bounds__(256, 3) k_pair(
    const float* __restrict__ xc, const float* __restrict__ yc,
    const float* __restrict__ mu, const float* __restrict__ istd,
    const float* __restrict__ w1p, const float* __restrict__ b1p)
{
    __shared__ union { Tables t; Reduce r; } sm;   // 40960 B
    __shared__ float sy[ND];                        //  2048 B

    const int tile = blockIdx.x, k = blockIdx.y, b = blockIdx.z;
    const int tid = threadIdx.x;

    const float PI2   = 6.2831853071795864f;
    const float ALPHA = 5.3364454f;   // 2pi*sqrt(0.5*log2(e))

    // ---- build full c-table (two points per thread), y folded into cos/sin ----
    #pragma unroll
    for (int c = tid; c < ND; c += 256) {
        const float x0 = xc[((b * ND + c) * 2 + 0) * NCHv + k];
        const float x1 = xc[((b * ND + c) * 2 + 1) * NCHv + k];
        const float y  = yc[(b * ND + c) * NCHv + k];
        float U0[4], U1[4], CO[4], SI[4], P[4];
        #pragma unroll
        for (int m = 0; m < NMIXv; m++) {
            const float u0 = x0 * istd[2 * m + 0] * ALPHA;
            const float u1 = x1 * istd[2 * m + 1] * ALPHA;
            float t = fmaf(x0, mu[2 * m + 0], x1 * mu[2 * m + 1]);
            t -= rintf(t);
            float sn, cn; __sincosf(PI2 * t, &sn, &cn);
            U0[m] = u0; U1[m] = u1; CO[m] = cn * y; SI[m] = sn * y;
            P[m] = -fmaf(u0, u0, u1 * u1);
        }
        sm.t.A[c] = make_float4(U0[0], U0[1], U1[0], U1[1]);
        sm.t.B[c] = make_float4(CO[0], CO[1], SI[0], SI[1]);
        sm.t.C[c] = make_float4(U0[2], U0[3], U1[2], U1[3]);
        sm.t.D[c] = make_float4(CO[2], CO[3], SI[2], SI[3]);
        sm.t.P[c] = make_float4(P[0], P[1], P[2], P[3]);
        sy[c] = y;
    }

    // ---- per-lane A-side values (scalar registers) ----
    const int al = tid & 31;
    const int cs = tid >> 5;          // c-split 0..7, uniform per warp
    const int a  = tile * 32 + al;

    float a00, a01, a02, a03;
    float a10, a11, a12, a13;
    float ca0, ca1, ca2, ca3;
    float sa0, sa1, sa2, sa3;
    float pa0, pa1, pa2, pa3;
    {
        const float x0 = xc[((b * ND + a) * 2 + 0) * NCHv + k];
        const float x1 = xc[((b * ND + a) * 2 + 1) * NCHv + k];
        float U0[4], U1[4], CO[4], SI[4], P[4];
        #pragma unroll
        for (int m = 0; m < NMIXv; m++) {
            const float u0 = x0 * istd[2 * m + 0] * ALPHA;
            const float u1 = x1 * istd[2 * m + 1] * ALPHA;
            float t = fmaf(x0, mu[2 * m + 0], x1 * mu[2 * m + 1]);
            t -= rintf(t);
            float sn, cn; __sincosf(PI2 * t, &sn, &cn);
            U0[m] = 2.0f * u0; U1[m] = 2.0f * u1; CO[m] = cn; SI[m] = sn;
            P[m] = -fmaf(u0, u0, u1 * u1);
        }
        a00 = U0[0]; a01 = U0[1]; a02 = U0[2]; a03 = U0[3];
        a10 = U1[0]; a11 = U1[1]; a12 = U1[2]; a13 = U1[3];
        ca0 = CO[0]; ca1 = CO[1]; ca2 = CO[2]; ca3 = CO[3];
        sa0 = SI[0]; sa1 = SI[1]; sa2 = SI[2]; sa3 = SI[3];
        pa0 = P[0];  pa1 = P[1];  pa2 = P[2];  pa3 = P[3];
    }
    __syncthreads();

    // ---- pair loop: warp = 32 a-lanes, 8 c-splits x 64 iters, scalar math ----
    float acc0 = 0.f, acc1 = 0.f, acc2 = 0.f, acc3 = 0.f;

    #pragma unroll 4
    for (int c = cs; c < ND; c += 8) {
        const float4 A = sm.t.A[c];
        const float4 B = sm.t.B[c];
        const float4 C = sm.t.C[c];
        const float4 D = sm.t.D[c];
        const float4 P = sm.t.P[c];
        {
            float s = pa0 + P.x;
            s = fmaf(A.x, a00, s);
            s = fmaf(A.z, a10, s);
            const float cv = fmaf(B.x, ca0, B.z * sa0);
            acc0 = fmaf(ex2f(s), cv, acc0);
        }
        {
            float s = pa1 + P.y;
            s = fmaf(A.y, a01, s);
            s = fmaf(A.w, a11, s);
            const float cv = fmaf(B.y, ca1, B.w * sa1);
            acc1 = fmaf(ex2f(s), cv, acc1);
        }
        {
            float s = pa2 + P.z;
            s = fmaf(C.x, a02, s);
            s = fmaf(C.z, a12, s);
            const float cv = fmaf(D.x, ca2, D.z * sa2);
            acc2 = fmaf(ex2f(s), cv, acc2);
        }
        {
            float s = pa3 + P.w;
            s = fmaf(C.y, a03, s);
            s = fmaf(C.w, a13, s);
            const float cv = fmaf(D.y, ca3, D.w * sa3);
            acc3 = fmaf(ex2f(s), cv, acc3);
        }
    }

    __syncthreads();   // tables dead; Reduce aliases them
    sm.r.red[cs][al][0] = acc0;
    sm.r.red[cs][al][1] = acc1;
    sm.r.red[cs][al][2] = acc2;
    sm.r.red[cs][al][3] = acc3;
    __syncthreads();

    // ---- reduce 8 c-splits, add zitter ----
    if (tid < 128) {
        const int lane = tid >> 2, m = tid & 3;
        float f = sm.r.red[0][lane][m];
        #pragma unroll
        for (int s = 1; s < 8; s++) f += sm.r.red[s][lane][m];
        f += 1.0e-4f * sy[tile * 32 + lane];
        sm.r.red[0][lane][m] = f;
    }
    __syncthreads();

    // ---- fused layer 1 on this tile's 32 a's ----
    {
        const int j = tid & 127, q = tid >> 7;
        const float wv0 = w1p[j * 5 + 0], wv1 = w1p[j * 5 + 1], wv2 = w1p[j * 5 + 2];
        const float wv3 = w1p[j * 5 + 3], wv4 = w1p[j * 5 + 4], bb = b1p[j];
        float acc = 0.f;
        #pragma unroll
        for (int aa = 0; aa < 16; aa++) {
            const int lane = q * 16 + aa;
            const float4 f = *(const float4*)&sm.r.red[0][lane][0];
            const float y = sy[tile * 32 + lane];
            float h = fmaf(wv0, f.x, bb);
            h = fmaf(wv1, f.y, h);
            h = fmaf(wv2, f.z, h);
            h = fmaf(wv3, f.w, h);
            h = fmaf(wv4, y, h);
            acc += fmaxf(h, 0.f);
        }
        sm.r.sred[q][j] = acc;
    }
    __syncthreads();
    if (tid < HD) {
        g_part[((b * NCHv + k) * NTILE + tile) * HD + tid] =
            sm.r.sred[0][tid] + sm.r.sred[1][tid];
    }
}

// ---------------- kernel 2: tile reduce + layers 2..5, with entry prefetch ----
// grid 8 (batch), 512 threads. L1 is flushed per launch (sm_10x), so every
// stage's weight loads were serial cold round-trips. Prefetch ALL lines up
// front (independent, no register pressure) so stage latencies overlap.
__global__ void __launch_bounds__(512) k_tail(
    const float* __restrict__ w2, const float* __restrict__ b2,
    const float* __restrict__ w3, const float* __restrict__ b3,
    const float* __restrict__ w4, const float* __restrict__ b4,
    const float* __restrict__ w5, const float* __restrict__ b5,
    float* __restrict__ out)
{
    __shared__ float sred[4][HD];
    __shared__ __align__(16) float h1[NCHv * HD];
    __shared__ __align__(16) float h2[HD];
    __shared__ __align__(16) float h3[HD];
    __shared__ float out5[NCHv * NMIXv][4];

    const int b = blockIdx.x, tid = threadIdx.x;
    const int j = tid & 127, q = tid >> 7;

    // ---- entry prefetch: every line this block will touch ----
    {
        // g_part slice for this batch: 6144 floats = 192 lines -> L1
        const float* gp = &g_part[(b * NCHv) * NTILE * HD];
        for (int i = tid * 32; i < NCHv * NTILE * HD; i += 512 * 32) pfL1(gp + i);
        // w3, w4: 16384 floats each = 512 lines -> L1
        for (int i = tid * 32; i < HD * HD; i += 512 * 32) { pfL1(w3 + i); pfL1(w4 + i); }
        // w5 + biases -> L1
        if (tid < 48) pfL1(w5 + tid * 32);
        if (tid < 4)  pfL1(b2 + tid * 32);
        if (tid < 4)  pfL1(b3 + tid * 32);
        if (tid < 4)  pfL1(b4 + tid * 32);
        if (tid == 0) pfL1(b5);
        // w2: 49152 floats = 1536 lines (192 KB, exceeds L1) -> L2
        for (int i = tid * 32; i < HD * NCHv * HD; i += 512 * 32) pfL2(w2 + i);
    }

    // reduce 16 tile-partials per (k,j) -> h1 (mean over 512 a)
    if (tid < NCHv * HD) {
        const int kk = tid >> 7, jj = tid & 127;
        const float* p = &g_part[((b * NCHv + kk) * NTILE) * HD + jj];
        float acc = 0.f;
        #pragma unroll
        for (int t = 0; t < NTILE; t++) acc += p[t * HD];
        h1[tid] = acc * (1.0f / 512.0f);
    }
    __syncthreads();

    // layer 2: 384 -> 128
    {
        float acc0 = 0.f, acc1 = 0.f;
        const float4* wr = (const float4*)(w2 + j * (NCHv * HD) + q * 96);
        const float4* xv = (const float4*)(h1 + q * 96);
        #pragma unroll 12
        for (int i = 0; i < 24; i += 2) {
            { const float4 w = wr[i], x = xv[i];
              acc0 = fmaf(w.x, x.x, acc0); acc0 = fmaf(w.y, x.y, acc0);
              acc0 = fmaf(w.z, x.z, acc0); acc0 = fmaf(w.w, x.w, acc0); }
            { const float4 w = wr[i+1], x = xv[i+1];
              acc1 = fmaf(w.x, x.x, acc1); acc1 = fmaf(w.y, x.y, acc1);
              acc1 = fmaf(w.z, x.z, acc1); acc1 = fmaf(w.w, x.w, acc1); }
        }
        sred[q][j] = acc0 + acc1;
        __syncthreads();
        if (tid < HD)
            h2[tid] = fmaxf(sred[0][tid] + sred[1][tid] + sred[2][tid] + sred[3][tid]
                            + b2[tid], 0.f);
        __syncthreads();
    }

    // layer 3: 128 -> 128
    {
        float acc0 = 0.f;
        const float4* wr = (const float4*)(w3 + j * HD + q * 32);
        const float4* xv = (const float4*)(h2 + q * 32);
        #pragma unroll
        for (int i = 0; i < 8; i++) {
            const float4 w = wr[i], x = xv[i];
            acc0 = fmaf(w.x, x.x, acc0); acc0 = fmaf(w.y, x.y, acc0);
            acc0 = fmaf(w.z, x.z, acc0); acc0 = fmaf(w.w, x.w, acc0);
        }
        sred[q][j] = acc0;
        __syncthreads();
        if (tid < HD)
            h3[tid] = fmaxf(sred[0][tid] + sred[1][tid] + sred[2][tid] + sred[3][tid]
                            + b3[tid], 0.f);
        __syncthreads();
    }

    // layer 4: 128 -> 128 (into h2)
    {
        float acc0 = 0.f;
        const float4* wr = (const float4*)(w4 + j * HD + q * 32);
        const float4* xv = (const float4*)(h3 + q * 32);
        #pragma unroll
        for (int i = 0; i < 8; i++) {
            const float4 w = wr[i], x = xv[i];
            acc0 = fmaf(w.x, x.x, acc0); acc0 = fmaf(w.y, x.y, acc0);
            acc0 = fmaf(w.z, x.z, acc0); acc0 = fmaf(w.w, x.w, acc0);
        }
        sred[q][j] = acc0;
        __syncthreads();
        if (tid < HD)
            h2[tid] = fmaxf(sred[0][tid] + sred[1][tid] + sred[2][tid] + sred[3][tid]
                            + b4[tid], 0.f);
        __syncthreads();
    }

    // layer 5: 128 -> 12
    if (tid < NCHv * NMIXv * 4) {
        const int j5 = tid >> 2, p = tid & 3;
        float acc = 0.f;
        const float4* wr = (const float4*)(w5 + j5 * HD + p * 32);
        const float4* xv = (const float4*)(h2 + p * 32);
        #pragma unroll
        for (int i = 0; i < 8; i++) {
            const float4 w = wr[i], x = xv[i];
            acc = fmaf(w.x, x.x, acc); acc = fmaf(w.y, x.y, acc);
            acc = fmaf(w.z, x.z, acc); acc = fmaf(w.w, x.w, acc);
        }
        out5[j5][p] = acc;
    }
    __syncthreads();
    if (tid < NCHv * NMIXv)
        out[b * (NCHv * NMIXv) + tid] =
            out5[tid][0] + out5[tid][1] + out5[tid][2] + out5[tid][3] + b5[tid];
}

// ---------------- launch ----------------
extern "C" void kernel_launch(void* const* d_in, const int* in_sizes, int n_in,
                              void* d_out, int out_size)
{
    const float* xc   = (const float*)d_in[0];
    const float* yc   = (const float*)d_in[1];
    const float* mu   = (const float*)d_in[2];
    const float* istd = (const float*)d_in[3];
    const float* w1   = (const float*)d_in[4];
    const float* b1   = (const float*)d_in[5];
    const float* w2   = (const float*)d_in[6];
    const float* b2   = (const float*)d_in[7];
    const float* w3   = (const float*)d_in[8];
    const float* b3   = (const float*)d_in[9];
    const float* w4   = (const float*)d_in[10];
    const float* b4   = (const float*)d_in[11];
    const float* w5   = (const float*)d_in[12];
    const float* b5   = (const float*)d_in[13];
    float* out = (float*)d_out;

    dim3 g1(NTILE, NCHv, NBv);   // 16 x 3 x 8 = 384 blocks, 256 threads
    k_pair<<<g1, 256>>>(xc, yc, mu, istd, w1, b1);
    k_tail<<<NBv, 512>>>(w2, b2, w3, b3, w4, b4, w5, b5, out);
}

// round 13
// speedup vs baseline: 1.0782x; 1.0782x over previous
#include <cuda_runtime.h>

#define NBv   8
#define ND    512
#define NCHv  3
#define NMIXv 4
#define HD    128
#define NTILE 16

// ---------------- device scratch ----------------
__device__ float g_part[NBv * NCHv * NTILE * HD];  // per-(b,k,tile) layer1 partials

__device__ __forceinline__ float ex2f(float x) {
    float r; asm("ex2.approx.f32 %0, %1;" : "=f"(r) : "f"(x)); return r;
}

// ---------------- shared-memory overlays ----------------
struct Tables {
    float4 A[ND];   // {u0m0, u0m1, u1m0, u1m1}
    float4 B[ND];   // {c0*y, c1*y, s0*y, s1*y}
    float4 C[ND];   // mixes 2,3 u's
    float4 D[ND];   // mixes 2,3 c*y / s*y
    float4 P[ND];   // {P0,P1,P2,P3}
};                                    // 40960 B
struct Reduce {
    float red[8][32][4];              // 4096 B  [csplit][lane][mix]
    float sred[2][HD];                // 1024 B
};

// ---------------- kernel 1: pair + fused layer 1 (R11 verbatim) ------------
__global__ void __launch_bounds__(256, 3) k_pair(
    const float* __restrict__ xc, const float* __restrict__ yc,
    const float* __restrict__ mu, const float* __restrict__ istd,
    const float* __restrict__ w1p, const float* __restrict__ b1p)
{
    __shared__ union { Tables t; Reduce r; } sm;   // 40960 B
    __shared__ float sy[ND];                        //  2048 B

    const int tile = blockIdx.x, k = blockIdx.y, b = blockIdx.z;
    const int tid = threadIdx.x;

    const float PI2   = 6.2831853071795864f;
    const float ALPHA = 5.3364454f;   // 2pi*sqrt(0.5*log2(e))

    // ---- build full c-table (two points per thread), y folded into cos/sin ----
    #pragma unroll
    for (int c = tid; c < ND; c += 256) {
        const float x0 = xc[((b * ND + c) * 2 + 0) * NCHv + k];
        const float x1 = xc[((b * ND + c) * 2 + 1) * NCHv + k];
        const float y  = yc[(b * ND + c) * NCHv + k];
        float U0[4], U1[4], CO[4], SI[4], P[4];
        #pragma unroll
        for (int m = 0; m < NMIXv; m++) {
            const float u0 = x0 * istd[2 * m + 0] * ALPHA;
            const float u1 = x1 * istd[2 * m + 1] * ALPHA;
            float t = fmaf(x0, mu[2 * m + 0], x1 * mu[2 * m + 1]);
            t -= rintf(t);
            float sn, cn; __sincosf(PI2 * t, &sn, &cn);
            U0[m] = u0; U1[m] = u1; CO[m] = cn * y; SI[m] = sn * y;
            P[m] = -fmaf(u0, u0, u1 * u1);
        }
        sm.t.A[c] = make_float4(U0[0], U0[1], U1[0], U1[1]);
        sm.t.B[c] = make_float4(CO[0], CO[1], SI[0], SI[1]);
        sm.t.C[c] = make_float4(U0[2], U0[3], U1[2], U1[3]);
        sm.t.D[c] = make_float4(CO[2], CO[3], SI[2], SI[3]);
        sm.t.P[c] = make_float4(P[0], P[1], P[2], P[3]);
        sy[c] = y;
    }

    // ---- per-lane A-side values (scalar registers) ----
    const int al = tid & 31;
    const int cs = tid >> 5;          // c-split 0..7, uniform per warp
    const int a  = tile * 32 + al;

    float a00, a01, a02, a03;
    float a10, a11, a12, a13;
    float ca0, ca1, ca2, ca3;
    float sa0, sa1, sa2, sa3;
    float pa0, pa1, pa2, pa3;
    {
        const float x0 = xc[((b * ND + a) * 2 + 0) * NCHv + k];
        const float x1 = xc[((b * ND + a) * 2 + 1) * NCHv + k];
        float U0[4], U1[4], CO[4], SI[4], P[4];
        #pragma unroll
        for (int m = 0; m < NMIXv; m++) {
            const float u0 = x0 * istd[2 * m + 0] * ALPHA;
            const float u1 = x1 * istd[2 * m + 1] * ALPHA;
            float t = fmaf(x0, mu[2 * m + 0], x1 * mu[2 * m + 1]);
            t -= rintf(t);
            float sn, cn; __sincosf(PI2 * t, &sn, &cn);
            U0[m] = 2.0f * u0; U1[m] = 2.0f * u1; CO[m] = cn; SI[m] = sn;
            P[m] = -fmaf(u0, u0, u1 * u1);
        }
        a00 = U0[0]; a01 = U0[1]; a02 = U0[2]; a03 = U0[3];
        a10 = U1[0]; a11 = U1[1]; a12 = U1[2]; a13 = U1[3];
        ca0 = CO[0]; ca1 = CO[1]; ca2 = CO[2]; ca3 = CO[3];
        sa0 = SI[0]; sa1 = SI[1]; sa2 = SI[2]; sa3 = SI[3];
        pa0 = P[0];  pa1 = P[1];  pa2 = P[2];  pa3 = P[3];
    }
    __syncthreads();

    // ---- pair loop: warp = 32 a-lanes, 8 c-splits x 64 iters, scalar math ----
    float acc0 = 0.f, acc1 = 0.f, acc2 = 0.f, acc3 = 0.f;

    #pragma unroll 4
    for (int c = cs; c < ND; c += 8) {
        const float4 A = sm.t.A[c];
        const float4 B = sm.t.B[c];
        const float4 C = sm.t.C[c];
        const float4 D = sm.t.D[c];
        const float4 P = sm.t.P[c];
        {
            float s = pa0 + P.x;
            s = fmaf(A.x, a00, s);
            s = fmaf(A.z, a10, s);
            const float cv = fmaf(B.x, ca0, B.z * sa0);
            acc0 = fmaf(ex2f(s), cv, acc0);
        }
        {
            float s = pa1 + P.y;
            s = fmaf(A.y, a01, s);
            s = fmaf(A.w, a11, s);
            const float cv = fmaf(B.y, ca1, B.w * sa1);
            acc1 = fmaf(ex2f(s), cv, acc1);
        }
        {
            float s = pa2 + P.z;
            s = fmaf(C.x, a02, s);
            s = fmaf(C.z, a12, s);
            const float cv = fmaf(D.x, ca2, D.z * sa2);
            acc2 = fmaf(ex2f(s), cv, acc2);
        }
        {
            float s = pa3 + P.w;
            s = fmaf(C.y, a03, s);
            s = fmaf(C.w, a13, s);
            const float cv = fmaf(D.y, ca3, D.w * sa3);
            acc3 = fmaf(ex2f(s), cv, acc3);
        }
    }

    __syncthreads();   // tables dead; Reduce aliases them
    sm.r.red[cs][al][0] = acc0;
    sm.r.red[cs][al][1] = acc1;
    sm.r.red[cs][al][2] = acc2;
    sm.r.red[cs][al][3] = acc3;
    __syncthreads();

    // ---- reduce 8 c-splits, add zitter ----
    if (tid < 128) {
        const int lane = tid >> 2, m = tid & 3;
        float f = sm.r.red[0][lane][m];
        #pragma unroll
        for (int s = 1; s < 8; s++) f += sm.r.red[s][lane][m];
        f += 1.0e-4f * sy[tile * 32 + lane];
        sm.r.red[0][lane][m] = f;
    }
    __syncthreads();

    // ---- fused layer 1 on this tile's 32 a's ----
    {
        const int j = tid & 127, q = tid >> 7;
        const float wv0 = w1p[j * 5 + 0], wv1 = w1p[j * 5 + 1], wv2 = w1p[j * 5 + 2];
        const float wv3 = w1p[j * 5 + 3], wv4 = w1p[j * 5 + 4], bb = b1p[j];
        float acc = 0.f;
        #pragma unroll
        for (int aa = 0; aa < 16; aa++) {
            const int lane = q * 16 + aa;
            const float4 f = *(const float4*)&sm.r.red[0][lane][0];
            const float y = sy[tile * 32 + lane];
            float h = fmaf(wv0, f.x, bb);
            h = fmaf(wv1, f.y, h);
            h = fmaf(wv2, f.z, h);
            h = fmaf(wv3, f.w, h);
            h = fmaf(wv4, y, h);
            acc += fmaxf(h, 0.f);
        }
        sm.r.sred[q][j] = acc;
    }
    __syncthreads();
    if (tid < HD) {
        g_part[((b * NCHv + k) * NTILE + tile) * HD + tid] =
            sm.r.sred[0][tid] + sm.r.sred[1][tid];
    }
}

// ---------------- kernel 2: tile reduce + layers 2..5, register-preloaded ----
// grid 8 (batch), 512 threads. All w3/w4/w5/bias data is loaded into REGISTERS
// at entry (real loads, not hints), so the 6 serial stages collapse to ~2
// memory exposures (g_part reduce + w2 in layer 2).
__global__ void __launch_bounds__(512) k_tail(
    const float* __restrict__ w2, const float* __restrict__ b2,
    const float* __restrict__ w3, const float* __restrict__ b3,
    const float* __restrict__ w4, const float* __restrict__ b4,
    const float* __restrict__ w5, const float* __restrict__ b5,
    float* __restrict__ out)
{
    __shared__ float sred[4][HD];
    __shared__ __align__(16) float h1[NCHv * HD];
    __shared__ __align__(16) float h2[HD];
    __shared__ __align__(16) float h3[HD];
    __shared__ float out5[NCHv * NMIXv][4];

    const int b = blockIdx.x, tid = threadIdx.x;
    const int j = tid & 127, q = tid >> 7;

    // ---- entry preloads (issued before any dependent work) ----
    float4 w3r[8], w4r[8];
    {
        const float4* p3 = (const float4*)(w3 + j * HD + q * 32);
        const float4* p4 = (const float4*)(w4 + j * HD + q * 32);
        #pragma unroll
        for (int i = 0; i < 8; i++) { w3r[i] = p3[i]; w4r[i] = p4[i]; }
    }
    float4 w5r[8];
    const int j5 = tid >> 2, p5 = tid & 3;
    if (tid < NCHv * NMIXv * 4) {
        const float4* p = (const float4*)(w5 + j5 * HD + p5 * 32);
        #pragma unroll
        for (int i = 0; i < 8; i++) w5r[i] = p[i];
    }
    const float bb2 = b2[j], bb3 = b3[j], bb4 = b4[j];
    const float bb5 = (tid < NCHv * NMIXv) ? b5[tid] : 0.f;

    // ---- reduce 16 tile-partials per (k,j) -> h1 (mean over 512 a) ----
    if (tid < NCHv * HD) {
        const int kk = tid >> 7, jj = tid & 127;
        const float* p = &g_part[((b * NCHv + kk) * NTILE) * HD + jj];
        float acc = 0.f;
        #pragma unroll
        for (int t = 0; t < NTILE; t++) acc += p[t * HD];
        h1[tid] = acc * (1.0f / 512.0f);
    }
    __syncthreads();

    // ---- layer 2: 384 -> 128 (w2 from gmem; only remaining gmem stage) ----
    {
        float acc0 = 0.f, acc1 = 0.f;
        const float4* wr = (const float4*)(w2 + j * (NCHv * HD) + q * 96);
        const float4* xv = (const float4*)(h1 + q * 96);
        #pragma unroll 12
        for (int i = 0; i < 24; i += 2) {
            { const float4 w = wr[i], x = xv[i];
              acc0 = fmaf(w.x, x.x, acc0); acc0 = fmaf(w.y, x.y, acc0);
              acc0 = fmaf(w.z, x.z, acc0); acc0 = fmaf(w.w, x.w, acc0); }
            { const float4 w = wr[i+1], x = xv[i+1];
              acc1 = fmaf(w.x, x.x, acc1); acc1 = fmaf(w.y, x.y, acc1);
              acc1 = fmaf(w.z, x.z, acc1); acc1 = fmaf(w.w, x.w, acc1); }
        }
        sred[q][j] = acc0 + acc1;
        __syncthreads();
        if (tid < HD)
            h2[tid] = fmaxf(sred[0][tid] + sred[1][tid] + sred[2][tid] + sred[3][tid]
                            + bb2, 0.f);
        __syncthreads();
    }

    // ---- layer 3: 128 -> 128 (weights in regs) ----
    {
        float acc0 = 0.f;
        const float4* xv = (const float4*)(h2 + q * 32);
        #pragma unroll
        for (int i = 0; i < 8; i++) {
            const float4 w = w3r[i], x = xv[i];
            acc0 = fmaf(w.x, x.x, acc0); acc0 = fmaf(w.y, x.y, acc0);
            acc0 = fmaf(w.z, x.z, acc0); acc0 = fmaf(w.w, x.w, acc0);
        }
        sred[q][j] = acc0;
        __syncthreads();
        if (tid < HD)
            h3[tid] = fmaxf(sred[0][tid] + sred[1][tid] + sred[2][tid] + sred[3][tid]
                            + bb3, 0.f);
        __syncthreads();
    }

    // ---- layer 4: 128 -> 128 (weights in regs, into h2) ----
    {
        float acc0 = 0.f;
        const float4* xv = (const float4*)(h3 + q * 32);
        #pragma unroll
        for (int i = 0; i < 8; i++) {
            const float4 w = w4r[i], x = xv[i];
            acc0 = fmaf(w.x, x.x, acc0); acc0 = fmaf(w.y, x.y, acc0);
            acc0 = fmaf(w.z, x.z, acc0); acc0 = fmaf(w.w, x.w, acc0);
        }
        sred[q][j] = acc0;
        __syncthreads();
        if (tid < HD)
            h2[tid] = fmaxf(sred[0][tid] + sred[1][tid] + sred[2][tid] + sred[3][tid]
                            + bb4, 0.f);
        __syncthreads();
    }

    // ---- layer 5: 128 -> 12 (weights in regs) ----
    if (tid < NCHv * NMIXv * 4) {
        float acc = 0.f;
        const float4* xv = (const float4*)(h2 + p5 * 32);
        #pragma unroll
        for (int i = 0; i < 8; i++) {
            const float4 w = w5r[i], x = xv[i];
            acc = fmaf(w.x, x.x, acc); acc = fmaf(w.y, x.y, acc);
            acc = fmaf(w.z, x.z, acc); acc = fmaf(w.w, x.w, acc);
        }
        out5[j5][p5] = acc;
    }
    __syncthreads();
    if (tid < NCHv * NMIXv)
        out[b * (NCHv * NMIXv) + tid] =
            out5[tid][0] + out5[tid][1] + out5[tid][2] + out5[tid][3] + bb5;
}

// ---------------- launch ----------------
extern "C" void kernel_launch(void* const* d_in, const int* in_sizes, int n_in,
                              void* d_out, int out_size)
{
    const float* xc   = (const float*)d_in[0];
    const float* yc   = (const float*)d_in[1];
    const float* mu   = (const float*)d_in[2];
    const float* istd = (const float*)d_in[3];
    const float* w1   = (const float*)d_in[4];
    const float* b1   = (const float*)d_in[5];
    const float* w2   = (const float*)d_in[6];
    const float* b2   = (const float*)d_in[7];
    const float* w3   = (const float*)d_in[8];
    const float* b3   = (const float*)d_in[9];
    const float* w4   = (const float*)d_in[10];
    const float* b4   = (const float*)d_in[11];
    const float* w5   = (const float*)d_in[12];
    const float* b5   = (const float*)d_in[13];
    float* out = (float*)d_out;

    dim3 g1(NTILE, NCHv, NBv);   // 16 x 3 x 8 = 384 blocks, 256 threads
    k_pair<<<g1, 256>>>(xc, yc, mu, istd, w1, b1);
    k_tail<<<NBv, 512>>>(w2, b2, w3, b3, w4, b4, w5, b5, out);
}